// round 1
// baseline (speedup 1.0000x reference)
#include <cuda_runtime.h>
#include <cuda_bf16.h>

// HMM forward algorithm, scaled (probability-domain) formulation.
//   w_0[j]   = exp(start[j]) * exp(emit[j, obs[0]])
//   w_t[j]   = (sum_i w_{t-1}[i] * exp(trans[i,j])) * inv_norm_t * exp(emit[j, obs[t]])
//   answer   = log(sum_j w_T[j]) + sum_t log(norm_t)
//
// Persistent kernel: 128 CTAs (one wave, all co-resident), each CTA owns 8
// output columns of exp(trans) pinned in SMEM. Per step: 8192 MACs per CTA,
// 32B chunk write, grid sync via a monotonically increasing release/acquire
// counter in L2. Normalization (block max) only every 8 steps (fp32 range
// safely bounds 8 unnormalized steps: growth <= 2^10/step).

#define S     1024
#define NOBS  4096
#define TT    8192
#define KCTA  128          // persistent CTAs (<= 148 SMs -> single wave)
#define CCOL  8            // output columns per CTA  (S / KCTA)
#define NTHR  256          // 8 warps

__device__ __align__(16) float g_emitT[TT * S];   // exp(emit[j, obs[t]]) gathered: [t][j]
__device__ __align__(16) float g_w[2][S];         // double-buffered state vector
__device__ unsigned int g_counter;

__device__ __forceinline__ void red_release_add(unsigned int* p) {
    asm volatile("red.release.gpu.global.add.u32 [%0], 1;" :: "l"(p) : "memory");
}
__device__ __forceinline__ unsigned int ld_acquire(const unsigned int* p) {
    unsigned int v;
    asm volatile("ld.acquire.gpu.global.u32 %0, [%1];" : "=r"(v) : "l"(p) : "memory");
    return v;
}

// Prologue: gather per-timestep emission probs (exp), init w0, reset counter.
__global__ void hmm_init_kernel(const int* __restrict__ obs,
                                const float* __restrict__ start,
                                const float* __restrict__ emit) {
    long idx = (long)blockIdx.x * blockDim.x + threadIdx.x;
    if (idx == 0) g_counter = 0u;
    if (idx >= (long)TT * S) return;
    int t = (int)(idx >> 10);
    int j = (int)(idx & (S - 1));
    float e = expf(emit[(long)j * NOBS + obs[t]]);
    g_emitT[idx] = e;
    if (t == 0) g_w[0][j] = expf(start[j]) * e;
}

__global__ void __launch_bounds__(NTHR, 1)
hmm_main_kernel(const float* __restrict__ trans, float* __restrict__ out) {
    __shared__ __align__(16) float P_s[CCOL][S];         // 32 KB: exp(trans) column slice
    __shared__ __align__(16) float w_s[S];               // 4 KB: current state vector
    __shared__ float red_s[(NTHR / 32) * CCOL];          // cross-warp partial sums
    __shared__ float max_s[NTHR / 32];

    const int tid  = threadIdx.x;
    const int cta  = blockIdx.x;
    const int wid  = tid >> 5;
    const int lane = tid & 31;
    const int j0   = cta * CCOL;

    // Load this CTA's 8 columns of exp(trans) into SMEM (one time).
    for (int idx = tid; idx < CCOL * S; idx += NTHR) {
        int i = idx >> 3;            // source state (row)
        int j = idx & (CCOL - 1);    // local output column
        P_s[j][i] = expf(trans[(long)i * S + j0 + j]);
    }
    __syncthreads();

    float logscale = 0.0f;   // meaningful on cta 0 only

    for (int t = 1; t < TT; ++t) {
        const int rb = (t - 1) & 1;
        const int wb = t & 1;

        // Prefetch emission values for this CTA's outputs (hide DRAM latency).
        float e_val = 0.0f;
        if (tid < CCOL) e_val = __ldg(&g_emitT[t * S + j0 + tid]);

        // Reload full state vector into SMEM (L2-hot, 4 KB).
        const float4 wv = *reinterpret_cast<const float4*>(&g_w[rb][tid << 2]);
        *reinterpret_cast<float4*>(&w_s[tid << 2]) = wv;

        float inv_norm = 1.0f;
        if (((t - 1) & 7) == 0) {
            // Every 8th step: global max for rescaling (identical in every CTA).
            float m = fmaxf(fmaxf(wv.x, wv.y), fmaxf(wv.z, wv.w));
            #pragma unroll
            for (int off = 16; off; off >>= 1)
                m = fmaxf(m, __shfl_xor_sync(0xffffffffu, m, off));
            if (lane == 0) max_s[wid] = m;
            __syncthreads();   // also covers w_s visibility
            m = max_s[0];
            #pragma unroll
            for (int ww = 1; ww < NTHR / 32; ++ww) m = fmaxf(m, max_s[ww]);
            inv_norm = 1.0f / m;
            if (cta == 0) logscale += logf(m);
        } else {
            __syncthreads();   // w_s visibility
        }

        // GEMV: warp `wid` covers source states [wid*128, wid*128+128),
        // each lane a contiguous float4; accumulate all 8 local columns.
        const int ib = (wid << 7) + (lane << 2);
        const float4 wq = *reinterpret_cast<const float4*>(&w_s[ib]);
        float acc[CCOL];
        #pragma unroll
        for (int j = 0; j < CCOL; ++j) {
            const float4 p = *reinterpret_cast<const float4*>(&P_s[j][ib]);
            acc[j] = wq.x * p.x + wq.y * p.y + wq.z * p.z + wq.w * p.w;
        }
        #pragma unroll
        for (int off = 16; off; off >>= 1) {
            #pragma unroll
            for (int j = 0; j < CCOL; ++j)
                acc[j] += __shfl_xor_sync(0xffffffffu, acc[j], off);
        }
        if (lane == 0) {
            #pragma unroll
            for (int j = 0; j < CCOL; ++j) red_s[wid * CCOL + j] = acc[j];
        }
        __syncthreads();

        if (tid < CCOL) {
            float s = 0.0f;
            #pragma unroll
            for (int ww = 0; ww < NTHR / 32; ++ww) s += red_s[ww * CCOL + tid];
            g_w[wb][j0 + tid] = s * inv_norm * e_val;
        }
        __syncthreads();   // order chunk STG before thread 0's release

        if (tid == 0) {
            red_release_add(&g_counter);
            const unsigned int target = (unsigned int)KCTA * (unsigned int)t;
            while (ld_acquire(&g_counter) < target) { }
        }
        __syncthreads();   // block waits on thread 0's acquire
    }

    // Final log-sum-exp (cta 0).
    if (cta == 0) {
        const float4 fv = *reinterpret_cast<const float4*>(&g_w[(TT - 1) & 1][tid << 2]);
        float s = fv.x + fv.y + fv.z + fv.w;
        #pragma unroll
        for (int off = 16; off; off >>= 1) s += __shfl_xor_sync(0xffffffffu, s, off);
        if (lane == 0) max_s[wid] = s;
        __syncthreads();
        if (tid == 0) {
            float tot = 0.0f;
            #pragma unroll
            for (int ww = 0; ww < NTHR / 32; ++ww) tot += max_s[ww];
            out[0] = logf(tot) + logscale;
        }
    }
}

extern "C" void kernel_launch(void* const* d_in, const int* in_sizes, int n_in,
                              void* d_out, int out_size) {
    const int*   obs   = (const int*)d_in[0];
    const float* start = (const float*)d_in[1];
    const float* trans = (const float*)d_in[2];
    const float* emit  = (const float*)d_in[3];
    float*       out   = (float*)d_out;

    (void)in_sizes; (void)n_in; (void)out_size;

    const int init_blocks = (TT * S + 255) / 256;
    hmm_init_kernel<<<init_blocks, 256>>>(obs, start, emit);
    hmm_main_kernel<<<KCTA, NTHR>>>(trans, out);
}